// round 4
// baseline (speedup 1.0000x reference)
#include <cuda_runtime.h>
#include <math.h>

// ---------------------------------------------------------------------------
// FIRE bias: out[h,s,t] = b2[h] + sum_w w2[h,w] * relu(w1[w]*nd(s,t) + b1[w])
// nd(s,t) = log((|s-t|+EPS)*c + 1+EPS) / log(|c*(max(s,thr)+EPS)| + 1+EPS)
//
// Single fused kernel: each block (one s-row) rebuilds the tiny piecewise-
// affine representation of the MLP in shared memory (sorted breakpoints
// -b1/w1 + per-interval (A,C) via an incremental relu-toggle walk), then
// streams out[h,s,:] with float4 streaming stores. nd is computed on the fly
// with fast __logf. Pure HBM-write-bound; exactly one kernel launch.
// ---------------------------------------------------------------------------

#define FIRE_EPS 1e-6f
#define FIRE_LOG_BIAS 1.0f
#define MAX_W 64
#define MAX_H 16

template <int H, int W>
__global__ void __launch_bounds__(512) fire_fused(
    float* __restrict__ out,
    const float* __restrict__ w1, const float* __restrict__ b1,
    const float* __restrict__ w2, const float* __restrict__ b2,
    const float* __restrict__ cp, const float* __restrict__ Lm,
    const float* __restrict__ iL, int S) {

    __shared__ float shT[W];                 // sorted breakpoints (+inf for sl==0)
    __shared__ float shA[(W + 1) * H];       // per-interval slope per head
    __shared__ float shC[(W + 1) * H];       // per-interval offset per head
    __shared__ float s_sl[W], s_b1[W], s_traw[W];
    __shared__ int   s_unit[W];              // sorted position -> unit index
    __shared__ float s_w2[H * W];

    const int tid = threadIdx.x;
    const float c   = __ldg(cp);
    const float thr = fabsf(__ldg(Lm) * __ldg(iL));

    // ---- per-block setup (cheap, hidden under other blocks' stores) ----
    if (tid < W) {
        float sl = __ldg(w1 + tid);
        float bb = __ldg(b1 + tid);
        s_sl[tid] = sl;
        s_b1[tid] = bb;
        s_traw[tid] = (sl != 0.0f) ? (-bb / sl) : __int_as_float(0x7f800000);
    }
    for (int k = tid; k < H * W; k += blockDim.x) s_w2[k] = __ldg(w2 + k);
    __syncthreads();

    if (tid < W) {  // rank sort with index tie-break
        float tw = s_traw[tid];
        int r = 0;
        for (int v = 0; v < W; ++v) {
            float tv = s_traw[v];
            if (tv < tw || (tv == tw && v < tid)) r++;
        }
        shT[r] = tw;
        s_unit[r] = tid;
    }
    __syncthreads();

    if (tid < H) {  // incremental affine-coefficient walk, one thread per head
        const int h = tid;
        float A = 0.0f;
        float Cc = __ldg(b2 + h);
        // interval 0: nd below all breakpoints -> active iff sl<0, or (sl==0 && b1>0)
#pragma unroll
        for (int w = 0; w < W; ++w) {
            float sl = s_sl[w];
            bool act = (sl < 0.0f) || (sl == 0.0f && s_b1[w] > 0.0f);
            if (act) {
                float ww = s_w2[h * W + w];
                A  = fmaf(ww, sl, A);
                Cc = fmaf(ww, s_b1[w], Cc);
            }
        }
        shA[h] = A;
        shC[h] = Cc;
        // crossing sorted breakpoint i-1 toggles unit s_unit[i-1]:
        //   sl>0 -> activates (add), sl<0 -> deactivates (subtract), sl==0 -> no-op
#pragma unroll
        for (int i = 1; i <= W; ++i) {
            int u = s_unit[i - 1];
            float sl = s_sl[u];
            float ww = s_w2[h * W + u];
            if (sl > 0.0f) {
                A  = fmaf(ww, sl, A);
                Cc = fmaf(ww, s_b1[u], Cc);
            } else if (sl < 0.0f) {
                A  = fmaf(ww, -sl, A);
                Cc = fmaf(-ww, s_b1[u], Cc);
            }
            shA[i * H + h] = A;
            shC[i * H + h] = Cc;
        }
    }
    __syncthreads();

    // ---- streaming main loop: this block owns row s ----
    const int s = blockIdx.x;
    const float posn = fmaxf((float)s, thr) + FIRE_EPS;
    const float invln = __fdividef(1.0f, __logf(fabsf(c * posn) + FIRE_LOG_BIAS + FIRE_EPS));
    const size_t plane = (size_t)S * (size_t)S;
    const size_t rowbase = (size_t)s * (size_t)S;

    for (int t0 = tid * 4; t0 < S; t0 += blockDim.x * 4) {
        if (t0 + 3 < S) {
            float nd[4];
#pragma unroll
            for (int e = 0; e < 4; ++e) {
                int t = t0 + e;
                int d = (s >= t) ? (s - t) : (t - s);
                nd[e] = __logf(fmaf((float)d + FIRE_EPS, c, FIRE_LOG_BIAS + FIRE_EPS)) * invln;
            }
            float ndmin = fminf(fminf(nd[0], nd[1]), fminf(nd[2], nd[3]));
            float ndmax = fmaxf(fmaxf(nd[0], nd[1]), fmaxf(nd[2], nd[3]));

            // lower_bound: i = #{shT[k] < v}
            int lo = 0, hi = W;
            while (lo < hi) { int m = (lo + hi) >> 1; if (shT[m] < ndmin) lo = m + 1; else hi = m; }
            int imin = lo;
            lo = imin; hi = W;
            while (lo < hi) { int m = (lo + hi) >> 1; if (shT[m] < ndmax) lo = m + 1; else hi = m; }
            int imax = lo;

            size_t base = rowbase + (size_t)t0;
            if (imin == imax) {
                int r = imin * H;
#pragma unroll
                for (int h = 0; h < H; ++h) {
                    float a = shA[r + h];
                    float cc = shC[r + h];
                    float4 v;
                    v.x = fmaf(a, nd[0], cc);
                    v.y = fmaf(a, nd[1], cc);
                    v.z = fmaf(a, nd[2], cc);
                    v.w = fmaf(a, nd[3], cc);
                    __stcs(reinterpret_cast<float4*>(out + (size_t)h * plane + base), v);
                }
            } else {
                int row[4];
#pragma unroll
                for (int e = 0; e < 4; ++e) {
                    float v = nd[e];
                    int l = imin, hh = imax;
                    while (l < hh) { int m = (l + hh) >> 1; if (shT[m] < v) l = m + 1; else hh = m; }
                    row[e] = l * H;
                }
#pragma unroll
                for (int h = 0; h < H; ++h) {
                    float4 v;
                    v.x = fmaf(shA[row[0] + h], nd[0], shC[row[0] + h]);
                    v.y = fmaf(shA[row[1] + h], nd[1], shC[row[1] + h]);
                    v.z = fmaf(shA[row[2] + h], nd[2], shC[row[2] + h]);
                    v.w = fmaf(shA[row[3] + h], nd[3], shC[row[3] + h]);
                    __stcs(reinterpret_cast<float4*>(out + (size_t)h * plane + base), v);
                }
            }
        } else {
            // scalar tail (unused when S % 4 == 0)
            for (int t = t0; t < S; ++t) {
                int d = (s >= t) ? (s - t) : (t - s);
                float v = __logf(fmaf((float)d + FIRE_EPS, c, FIRE_LOG_BIAS + FIRE_EPS)) * invln;
                int lo = 0, hi = W;
                while (lo < hi) { int m = (lo + hi) >> 1; if (shT[m] < v) lo = m + 1; else hi = m; }
                for (int h = 0; h < H; ++h)
                    out[(size_t)h * plane + rowbase + t] = fmaf(shA[lo * H + h], v, shC[lo * H + h]);
            }
        }
    }
}

// ---- generic fallback (runtime H, W): correctness-first path -------------
__global__ void fire_generic(const float* __restrict__ w1, const float* __restrict__ b1,
                             const float* __restrict__ w2, const float* __restrict__ b2,
                             const float* __restrict__ cp, const float* __restrict__ Lm,
                             const float* __restrict__ iL,
                             float* __restrict__ out, int S, int W, int H) {
    int s = blockIdx.y;
    int t = blockIdx.x * blockDim.x + threadIdx.x;
    if (t >= S) return;
    float c = cp[0];
    float thr = fabsf(Lm[0] * iL[0]);
    int d = (s >= t) ? (s - t) : (t - s);
    float log_rel = logf(fmaf((float)d + FIRE_EPS, c, FIRE_LOG_BIAS + FIRE_EPS));
    float posn = fmaxf((float)s, thr) + FIRE_EPS;
    float nd = log_rel / logf(fabsf(c * posn) + FIRE_LOG_BIAS + FIRE_EPS);
    for (int h = 0; h < H; ++h) {
        float acc = b2[h];
        for (int w = 0; w < W; ++w) {
            float hv = fmaf(w1[w], nd, b1[w]);
            hv = fmaxf(hv, 0.0f);
            acc = fmaf(w2[h * W + w], hv, acc);
        }
        out[(size_t)h * S * S + (size_t)s * S + t] = acc;
    }
}

extern "C" void kernel_launch(void* const* d_in, const int* in_sizes, int n_in,
                              void* d_out, int out_size) {
    // inputs: x, w1, b1, w2, b2, c, L_multiplier, init_L  (x unused by the math)
    const float* w1 = (const float*)d_in[1];
    const float* b1 = (const float*)d_in[2];
    const float* w2 = (const float*)d_in[3];
    const float* b2 = (const float*)d_in[4];
    const float* c  = (const float*)d_in[5];
    const float* Lm = (const float*)d_in[6];
    const float* iL = (const float*)d_in[7];

    int W = in_sizes[1];          // w1 is (W,1)
    int H = in_sizes[4];          // b2 is (H,)
    long long ss = (long long)out_size / (long long)H;  // S*S
    int S = (int)(sqrt((double)ss) + 0.5);

    if (H == 12 && W == 32) {
        fire_fused<12, 32><<<S, 512>>>((float*)d_out, w1, b1, w2, b2, c, Lm, iL, S);
    } else {
        dim3 block(256);
        dim3 grid((unsigned)((S + 255) / 256), (unsigned)S);
        fire_generic<<<grid, block>>>(w1, b1, w2, b2, c, Lm, iL, (float*)d_out, S, W, H);
    }
}

// round 6
// speedup vs baseline: 1.0484x; 1.0484x over previous
#include <cuda_runtime.h>
#include <math.h>

// ---------------------------------------------------------------------------
// FIRE bias: out[h,s,t] = b2[h] + sum_w w2[h,w] * relu(w1[w]*nd(s,t) + b1[w])
// nd(s,t) = log((|s-t|+EPS)*c + 1+EPS) / log(|c*(max(s,thr)+EPS)| + 1+EPS)
//
// Single fused kernel, one block per s-row. Each block rebuilds the tiny
// piecewise-affine representation of the MLP in shared memory (sorted
// breakpoints -b1/w1 + per-interval (A,C) via an incremental relu-toggle
// walk), then streams out[h,s,:] with float4 streaming stores.
// __launch_bounds__(512, 4) pins regs<=32 so occupancy stays at 2048
// threads/SM — the R3 fusion lost 2x bandwidth to a 64-reg allocation.
// ---------------------------------------------------------------------------

#define FIRE_EPS 1e-6f
#define FIRE_LOG_BIAS 1.0f

template <int H, int W>
__global__ void __launch_bounds__(512, 4) fire_fused(
    float* __restrict__ out,
    const float* __restrict__ w1, const float* __restrict__ b1,
    const float* __restrict__ w2, const float* __restrict__ b2,
    const float* __restrict__ cp, const float* __restrict__ Lm,
    const float* __restrict__ iL, int S) {

    __shared__ float shT[W];                 // sorted breakpoints (+inf for sl==0)
    __shared__ float shA[(W + 1) * H];       // per-interval slope per head
    __shared__ float shC[(W + 1) * H];       // per-interval offset per head
    __shared__ float s_sl[W], s_b1[W], s_traw[W];
    __shared__ int   s_unit[W];              // sorted position -> unit index
    __shared__ float s_cinv[2];              // c, invln broadcast

    const int tid = threadIdx.x;

    // ---- per-block setup (cold path; spills here are fine) ----
    if (tid < W) {
        float sl = __ldg(w1 + tid);
        float bb = __ldg(b1 + tid);
        s_sl[tid] = sl;
        s_b1[tid] = bb;
        s_traw[tid] = (sl != 0.0f) ? (-bb / sl) : __int_as_float(0x7f800000);
    }
    if (tid == 0) {
        float c = __ldg(cp);
        float thr = fabsf(__ldg(Lm) * __ldg(iL));
        float posn = fmaxf((float)blockIdx.x, thr) + FIRE_EPS;
        s_cinv[0] = c;
        s_cinv[1] = __fdividef(1.0f, __logf(fabsf(c * posn) + FIRE_LOG_BIAS + FIRE_EPS));
    }
    __syncthreads();

    if (tid < W) {  // rank sort with index tie-break
        float tw = s_traw[tid];
        int r = 0;
        for (int v = 0; v < W; ++v) {
            float tv = s_traw[v];
            if (tv < tw || (tv == tw && v < tid)) r++;
        }
        shT[r] = tw;
        s_unit[r] = tid;
    }
    __syncthreads();

    if (tid < H) {  // incremental affine-coefficient walk, one thread per head
        const int h = tid;
        float A = 0.0f;
        float Cc = __ldg(b2 + h);
        // interval 0: nd below all breakpoints -> active iff sl<0 (or sl==0 && b1>0)
        for (int w = 0; w < W; ++w) {
            float sl = s_sl[w];
            bool act = (sl < 0.0f) || (sl == 0.0f && s_b1[w] > 0.0f);
            if (act) {
                float ww = __ldg(w2 + h * W + w);
                A  = fmaf(ww, sl, A);
                Cc = fmaf(ww, s_b1[w], Cc);
            }
        }
        shA[h] = A;
        shC[h] = Cc;
        // crossing sorted breakpoint i-1 toggles unit s_unit[i-1]:
        //   sl>0 activates (add), sl<0 deactivates (subtract), sl==0 no-op
        for (int i = 1; i <= W; ++i) {
            int u = s_unit[i - 1];
            float sl = s_sl[u];
            float ww = __ldg(w2 + h * W + u);
            if (sl > 0.0f) {
                A  = fmaf(ww, sl, A);
                Cc = fmaf(ww, s_b1[u], Cc);
            } else if (sl < 0.0f) {
                A  = fmaf(ww, -sl, A);
                Cc = fmaf(-ww, s_b1[u], Cc);
            }
            shA[i * H + h] = A;
            shC[i * H + h] = Cc;
        }
    }
    __syncthreads();

    // ---- hot streaming loop: this block owns row s ----
    const int s = blockIdx.x;
    const float c = s_cinv[0];
    const float invln = s_cinv[1];
    const size_t plane = (size_t)S * (size_t)S;
    const size_t rowbase = (size_t)s * (size_t)S;

    for (int t0 = tid * 4; t0 < S; t0 += blockDim.x * 4) {
        if (t0 + 3 < S) {
            float nd[4];
#pragma unroll
            for (int e = 0; e < 4; ++e) {
                int t = t0 + e;
                int d = (s >= t) ? (s - t) : (t - s);
                nd[e] = __logf(fmaf((float)d + FIRE_EPS, c, FIRE_LOG_BIAS + FIRE_EPS)) * invln;
            }
            float ndmin = fminf(fminf(nd[0], nd[1]), fminf(nd[2], nd[3]));
            float ndmax = fmaxf(fmaxf(nd[0], nd[1]), fmaxf(nd[2], nd[3]));

            // lower_bound: i = #{shT[k] < v}
            int lo = 0, hi = W;
            while (lo < hi) { int m = (lo + hi) >> 1; if (shT[m] < ndmin) lo = m + 1; else hi = m; }
            int imin = lo;
            lo = imin; hi = W;
            while (lo < hi) { int m = (lo + hi) >> 1; if (shT[m] < ndmax) lo = m + 1; else hi = m; }
            int imax = lo;

            size_t base = rowbase + (size_t)t0;
            if (imin == imax) {
                int r = imin * H;
#pragma unroll
                for (int h = 0; h < H; ++h) {
                    float a = shA[r + h];
                    float cc = shC[r + h];
                    float4 v;
                    v.x = fmaf(a, nd[0], cc);
                    v.y = fmaf(a, nd[1], cc);
                    v.z = fmaf(a, nd[2], cc);
                    v.w = fmaf(a, nd[3], cc);
                    __stcs(reinterpret_cast<float4*>(out + (size_t)h * plane + base), v);
                }
            } else {
                int row[4];
#pragma unroll
                for (int e = 0; e < 4; ++e) {
                    float v = nd[e];
                    int l = imin, hh = imax;
                    while (l < hh) { int m = (l + hh) >> 1; if (shT[m] < v) l = m + 1; else hh = m; }
                    row[e] = l * H;
                }
#pragma unroll
                for (int h = 0; h < H; ++h) {
                    float4 v;
                    v.x = fmaf(shA[row[0] + h], nd[0], shC[row[0] + h]);
                    v.y = fmaf(shA[row[1] + h], nd[1], shC[row[1] + h]);
                    v.z = fmaf(shA[row[2] + h], nd[2], shC[row[2] + h]);
                    v.w = fmaf(shA[row[3] + h], nd[3], shC[row[3] + h]);
                    __stcs(reinterpret_cast<float4*>(out + (size_t)h * plane + base), v);
                }
            }
        } else {
            // scalar tail (unused when S % 4 == 0)
            for (int t = t0; t < S; ++t) {
                int d = (s >= t) ? (s - t) : (t - s);
                float v = __logf(fmaf((float)d + FIRE_EPS, c, FIRE_LOG_BIAS + FIRE_EPS)) * invln;
                int lo = 0, hi = W;
                while (lo < hi) { int m = (lo + hi) >> 1; if (shT[m] < v) lo = m + 1; else hi = m; }
                for (int h = 0; h < H; ++h)
                    out[(size_t)h * plane + rowbase + t] = fmaf(shA[lo * H + h], v, shC[lo * H + h]);
            }
        }
    }
}

// ---- generic fallback (runtime H, W): correctness-first path -------------
__global__ void fire_generic(const float* __restrict__ w1, const float* __restrict__ b1,
                             const float* __restrict__ w2, const float* __restrict__ b2,
                             const float* __restrict__ cp, const float* __restrict__ Lm,
                             const float* __restrict__ iL,
                             float* __restrict__ out, int S, int W, int H) {
    int s = blockIdx.y;
    int t = blockIdx.x * blockDim.x + threadIdx.x;
    if (t >= S) return;
    float c = cp[0];
    float thr = fabsf(Lm[0] * iL[0]);
    int d = (s >= t) ? (s - t) : (t - s);
    float log_rel = logf(fmaf((float)d + FIRE_EPS, c, FIRE_LOG_BIAS + FIRE_EPS));
    float posn = fmaxf((float)s, thr) + FIRE_EPS;
    float nd = log_rel / logf(fabsf(c * posn) + FIRE_LOG_BIAS + FIRE_EPS);
    for (int h = 0; h < H; ++h) {
        float acc = b2[h];
        for (int w = 0; w < W; ++w) {
            float hv = fmaf(w1[w], nd, b1[w]);
            hv = fmaxf(hv, 0.0f);
            acc = fmaf(w2[h * W + w], hv, acc);
        }
        out[(size_t)h * S * S + (size_t)s * S + t] = acc;
    }
}

extern "C" void kernel_launch(void* const* d_in, const int* in_sizes, int n_in,
                              void* d_out, int out_size) {
    // inputs: x, w1, b1, w2, b2, c, L_multiplier, init_L  (x unused by the math)
    const float* w1 = (const float*)d_in[1];
    const float* b1 = (const float*)d_in[2];
    const float* w2 = (const float*)d_in[3];
    const float* b2 = (const float*)d_in[4];
    const float* c  = (const float*)d_in[5];
    const float* Lm = (const float*)d_in[6];
    const float* iL = (const float*)d_in[7];

    int W = in_sizes[1];          // w1 is (W,1)
    int H = in_sizes[4];          // b2 is (H,)
    long long ss = (long long)out_size / (long long)H;  // S*S
    int S = (int)(sqrt((double)ss) + 0.5);

    if (H == 12 && W == 32) {
        fire_fused<12, 32><<<S, 512>>>((float*)d_out, w1, b1, w2, b2, c, Lm, iL, S);
    } else {
        dim3 block(256);
        dim3 grid((unsigned)((S + 255) / 256), (unsigned)S);
        fire_generic<<<grid, block>>>(w1, b1, w2, b2, c, Lm, iL, (float*)d_out, S, W, H);
    }
}